// round 10
// baseline (speedup 1.0000x reference)
#include <cuda_runtime.h>
#include <math.h>

#define E_N 500000
#define G_N 256
#define H_N 256
#define H2_N 512
#define EPS_F 1.1920929e-07f
#define LOG_EPS -15.942385f
#define SEG_CAP 2560

// ---------------- scratch (device globals; no allocation allowed) ------------
__device__ float d_v_edge[H_N];        // att_vec @ W_edge
__device__ float d_v_query[H_N];       // att_vec @ W_query
__device__ float d_att_raw[E_N];       // post-leaky/bonus attention logits
__device__ float d_sum_tok[G_N * H_N]; // segment sums of raw edge tokens
__device__ int   d_seg[G_N + 1];       // segment bounds (sorted edge_batch)
__device__ float d_xn[G_N * H2_N];     // LayerNorm output
__device__ float d_h1[G_N * H_N];      // GELU(MLP hidden)

__device__ __forceinline__ float warp_sum(float v) {
    #pragma unroll
    for (int o = 16; o; o >>= 1) v += __shfl_xor_sync(0xffffffffu, v, o);
    return v;
}

// ---------------- kA: v_edge/v_query + zero sum_tok + segment bounds ---------
// grid 64 x 256 thr.  blocks 0-7: v_edge; 8-15: v_query; 16-31: zero; 32-63: seg
__global__ void kA_prep(const float* __restrict__ W_edge,
                        const float* __restrict__ W_query,
                        const float* __restrict__ att_vec,
                        const int* __restrict__ batch) {
    int b = blockIdx.x;
    int tid = threadIdx.x;
    if (b < 16) {
        const float* W = (b < 8) ? W_edge : W_query;
        float* v       = (b < 8) ? d_v_edge : d_v_query;
        int bx = b & 7;
        __shared__ float a[H_N];
        __shared__ float part[8][32];
        a[tid] = att_vec[tid];
        __syncthreads();
        int tt = tid & 31, jg = tid >> 5;
        int t0 = bx * 32 + tt;
        float s = 0.f;
        #pragma unroll 8
        for (int j = jg * 32; j < jg * 32 + 32; ++j)
            s = fmaf(a[j], W[j * H_N + t0], s);
        part[jg][tt] = s;
        __syncthreads();
        if (jg == 0) {
            float r = part[0][tt] + part[1][tt] + part[2][tt] + part[3][tt]
                    + part[4][tt] + part[5][tt] + part[6][tt] + part[7][tt];
            v[t0] = r;
        }
    } else if (b < 32) {
        int idx = (b - 16) * 256 + tid;
        for (int i = idx; i < G_N * H_N; i += 16 * 256) d_sum_tok[i] = 0.0f;
    } else {
        int idx = (b - 32) * 256 + tid;
        int stride = 32 * 256;
        for (int e = idx; e < E_N; e += stride) {
            int bc = batch[e];
            int bp = (e == 0) ? -1 : batch[e - 1];
            for (int g = bp + 1; g <= bc; ++g) d_seg[g] = e;
            if (e == E_N - 1)
                for (int g = bc + 1; g <= G_N; ++g) d_seg[g] = E_N;
        }
    }
}

// ---------------- K3: dominant streaming pass over edge_tokens ---------------
#define K3_BLOCK 256
#define K3_GRID  592
#define K3_WARPS (K3_GRID * (K3_BLOCK / 32))

__global__ __launch_bounds__(K3_BLOCK) void k3_edges(
        const float* __restrict__ tok,
        const float* __restrict__ question,
        const int* __restrict__ batch,
        const int* __restrict__ sel) {
    int warp = (blockIdx.x * blockDim.x + threadIdx.x) >> 5;
    int lane = threadIdx.x & 31;
    const int chunk = (E_N + K3_WARPS - 1) / K3_WARPS;
    int e0 = warp * chunk;
    int e1 = min(e0 + chunk, E_N);
    if (e0 >= e1) return;

    float4 v0 = ((const float4*)d_v_edge)[lane];
    float4 v1 = ((const float4*)d_v_edge)[lane + 32];
    float4 w0 = ((const float4*)d_v_query)[lane];
    float4 w1 = ((const float4*)d_v_query)[lane + 32];

    float4 a0 = make_float4(0.f, 0.f, 0.f, 0.f);
    float4 a1 = make_float4(0.f, 0.f, 0.f, 0.f);
    float keep = 0.f;

    const float4* base = (const float4*)tok;
    float4 t0 = __ldcs(base + (size_t)e0 * 64 + lane);
    float4 t1 = __ldcs(base + (size_t)e0 * 64 + 32 + lane);
    int g  = batch[e0];
    int cg = g;

    // q_att for the initial segment (warp-wide dot; result in all lanes)
    float qa;
    {
        const float4* q4 = (const float4*)(question + (size_t)g * H_N);
        float4 qa0 = q4[lane], qa1 = q4[lane + 32];
        float s = qa0.x * w0.x;
        s = fmaf(qa0.y, w0.y, s); s = fmaf(qa0.z, w0.z, s); s = fmaf(qa0.w, w0.w, s);
        s = fmaf(qa1.x, w1.x, s); s = fmaf(qa1.y, w1.y, s);
        s = fmaf(qa1.z, w1.z, s); s = fmaf(qa1.w, w1.w, s);
        qa = warp_sum(s);
    }

    for (int e = e0; e < e1; ++e) {
        float4 n0, n1; int ng = cg;
        if (e + 1 < e1) {
            n0 = __ldcs(base + (size_t)(e + 1) * 64 + lane);
            n1 = __ldcs(base + (size_t)(e + 1) * 64 + 32 + lane);
            ng = batch[e + 1];
        }
        if (g != cg) {  // segment boundary: flush partial sums, refresh qa
            float* dst = d_sum_tok + (size_t)cg * H_N;
            atomicAdd(&dst[4 * lane + 0], a0.x);
            atomicAdd(&dst[4 * lane + 1], a0.y);
            atomicAdd(&dst[4 * lane + 2], a0.z);
            atomicAdd(&dst[4 * lane + 3], a0.w);
            atomicAdd(&dst[128 + 4 * lane + 0], a1.x);
            atomicAdd(&dst[128 + 4 * lane + 1], a1.y);
            atomicAdd(&dst[128 + 4 * lane + 2], a1.z);
            atomicAdd(&dst[128 + 4 * lane + 3], a1.w);
            a0 = make_float4(0.f, 0.f, 0.f, 0.f);
            a1 = make_float4(0.f, 0.f, 0.f, 0.f);
            cg = g;
            const float4* q4 = (const float4*)(question + (size_t)g * H_N);
            float4 qa0 = q4[lane], qa1 = q4[lane + 32];
            float s = qa0.x * w0.x;
            s = fmaf(qa0.y, w0.y, s); s = fmaf(qa0.z, w0.z, s); s = fmaf(qa0.w, w0.w, s);
            s = fmaf(qa1.x, w1.x, s); s = fmaf(qa1.y, w1.y, s);
            s = fmaf(qa1.z, w1.z, s); s = fmaf(qa1.w, w1.w, s);
            qa = warp_sum(s);
        }
        a0.x += t0.x; a0.y += t0.y; a0.z += t0.z; a0.w += t0.w;
        a1.x += t1.x; a1.y += t1.y; a1.z += t1.z; a1.w += t1.w;

        float d = t0.x * v0.x;
        d = fmaf(t0.y, v0.y, d); d = fmaf(t0.z, v0.z, d); d = fmaf(t0.w, v0.w, d);
        d = fmaf(t1.x, v1.x, d); d = fmaf(t1.y, v1.y, d);
        d = fmaf(t1.z, v1.z, d); d = fmaf(t1.w, v1.w, d);
        float tot = warp_sum(d);   // full sum in all lanes

        float att = tot + qa;
        att = att > 0.f ? att : 0.2f * att;             // LeakyReLU(0.2)
        if (sel[e] == 0) att += 0.5f;                   // frontier bonus
        if (lane == (e & 31)) keep = att;

        // coalesced 128B store every 32 edges (range-guarded at head/tail)
        if ((e & 31) == 31 || e == e1 - 1) {
            int bse = e & ~31;
            int idx = bse + lane;
            if (idx >= e0 && idx <= e)
                d_att_raw[idx] = keep;
        }

        t0 = n0; t1 = n1; g = ng;
    }
    float* dst = d_sum_tok + (size_t)cg * H_N;
    atomicAdd(&dst[4 * lane + 0], a0.x);
    atomicAdd(&dst[4 * lane + 1], a0.y);
    atomicAdd(&dst[4 * lane + 2], a0.z);
    atomicAdd(&dst[4 * lane + 3], a0.w);
    atomicAdd(&dst[128 + 4 * lane + 0], a1.x);
    atomicAdd(&dst[128 + 4 * lane + 1], a1.y);
    atomicAdd(&dst[128 + 4 * lane + 2], a1.z);
    atomicAdd(&dst[128 + 4 * lane + 3], a1.w);
}

// ---------------- K4: softmax stats + edge logits, smem-cached, 512 thr ------
__global__ __launch_bounds__(512) void k4_fused(const int* __restrict__ sel,
                                                float* __restrict__ out_edge) {
    int gi = blockIdx.x, t = threadIdx.x;
    int start = d_seg[gi], end = d_seg[gi + 1];
    int n = end - start;

    __shared__ float red[512];
    __shared__ float satt[SEG_CAP];
    __shared__ unsigned char smsk[SEG_CAP];

    if (n <= SEG_CAP) {
        #pragma unroll 4
        for (int i = t; i < n; i += 512) {
            satt[i] = d_att_raw[start + i];
            smsk[i] = (unsigned char)(sel[start + i] != 0);
        }
        __syncthreads();

        float mx = -INFINITY;
        #pragma unroll 4
        for (int i = t; i < n; i += 512) mx = fmaxf(mx, satt[i]);
        red[t] = mx; __syncthreads();
        for (int s = 256; s; s >>= 1) { if (t < s) red[t] = fmaxf(red[t], red[t + s]); __syncthreads(); }
        mx = red[0];
        __syncthreads();

        float sm = 0.f;
        #pragma unroll 4
        for (int i = t; i < n; i += 512)
            if (!smsk[i]) sm += expf(satt[i] - mx);
        red[t] = sm; __syncthreads();
        for (int s = 256; s; s >>= 1) { if (t < s) red[t] += red[t + s]; __syncthreads(); }
        float sub = mx + logf(fmaxf(red[0], EPS_F));

        #pragma unroll 4
        for (int i = t; i < n; i += 512) {
            float v = LOG_EPS;
            if (!smsk[i]) v = fmaxf(satt[i] - sub, LOG_EPS);
            out_edge[start + i] = v;
        }
    } else {
        float mx = -INFINITY;
        for (int e = start + t; e < end; e += 512) mx = fmaxf(mx, d_att_raw[e]);
        red[t] = mx; __syncthreads();
        for (int s = 256; s; s >>= 1) { if (t < s) red[t] = fmaxf(red[t], red[t + s]); __syncthreads(); }
        mx = red[0];
        __syncthreads();

        float sm = 0.f;
        for (int e = start + t; e < end; e += 512)
            if (sel[e] == 0) sm += expf(d_att_raw[e] - mx);
        red[t] = sm; __syncthreads();
        for (int s = 256; s; s >>= 1) { if (t < s) red[t] += red[t + s]; __syncthreads(); }
        float sub = mx + logf(fmaxf(red[0], EPS_F));

        for (int e = start + t; e < end; e += 512) {
            float v = LOG_EPS;
            if (sel[e] == 0) v = fmaxf(d_att_raw[e] - sub, LOG_EPS);
            out_edge[e] = v;
        }
    }
}

// ---------------- K5: pooled = (sum_tok @ W_edge^T) / count  (tiled GEMM) ----
__global__ void k5_pool(const float* __restrict__ W_edge,
                        float* __restrict__ out_pool) {
    __shared__ float As[32][33], Ws[32][33];
    int tx = threadIdx.x, ty = threadIdx.y;
    float acc = 0.f;
    for (int kt = 0; kt < H_N; kt += 32) {
        As[ty][tx] = d_sum_tok[(blockIdx.y * 32 + ty) * H_N + kt + tx];
        Ws[ty][tx] = W_edge[(blockIdx.x * 32 + ty) * H_N + kt + tx];
        __syncthreads();
        #pragma unroll
        for (int kk = 0; kk < 32; ++kk) acc = fmaf(As[ty][kk], Ws[tx][kk], acc);
        __syncthreads();
    }
    int g = blockIdx.y * 32 + ty, j = blockIdx.x * 32 + tx;
    float invden = 1.0f / (float)max(d_seg[g + 1] - d_seg[g], 1);
    out_pool[g * H_N + j] = acc * invden;
}

// ---------------- K6a: LayerNorm over concat(pooled, question) ---------------
__global__ void k6a_ln(const float* __restrict__ pooled,
                       const float* __restrict__ q,
                       const float* __restrict__ ln_g,
                       const float* __restrict__ ln_b) {
    int g = blockIdx.x, t = threadIdx.x;
    float x0 = pooled[g * H_N + t];
    float x1 = q[g * H_N + t];
    __shared__ float rs[256], rss[256];
    rs[t]  = x0 + x1;
    rss[t] = x0 * x0 + x1 * x1;
    __syncthreads();
    for (int s = 128; s; s >>= 1) {
        if (t < s) { rs[t] += rs[t + s]; rss[t] += rss[t + s]; }
        __syncthreads();
    }
    float mu  = rs[0] * (1.0f / 512.0f);
    float var = rss[0] * (1.0f / 512.0f) - mu * mu;
    float inv = rsqrtf(var + 1e-5f);
    d_xn[g * H2_N + t]        = (x0 - mu) * inv * ln_g[t]        + ln_b[t];
    d_xn[g * H2_N + 256 + t]  = (x1 - mu) * inv * ln_g[256 + t]  + ln_b[256 + t];
}

// ---------------- K6b: h1 = GELU(xn @ W1^T + b1)  (tiled GEMM, K=512) --------
__global__ void k6b_mlp(const float* __restrict__ W1,
                        const float* __restrict__ b1) {
    __shared__ float As[32][33], Ws[32][33];
    int tx = threadIdx.x, ty = threadIdx.y;
    float acc = 0.f;
    for (int kt = 0; kt < H2_N; kt += 32) {
        As[ty][tx] = d_xn[(blockIdx.y * 32 + ty) * H2_N + kt + tx];
        Ws[ty][tx] = W1[(blockIdx.x * 32 + ty) * H2_N + kt + tx];
        __syncthreads();
        #pragma unroll
        for (int kk = 0; kk < 32; ++kk) acc = fmaf(As[ty][kk], Ws[tx][kk], acc);
        __syncthreads();
    }
    int g = blockIdx.y * 32 + ty, j = blockIdx.x * 32 + tx;
    float x = acc + b1[j];
    float gl = 0.5f * x * (1.0f + erff(x * 0.70710678118654752f)); // exact GELU
    d_h1[g * H_N + j] = gl;
}

// ---------------- K6c: stop_logits = h1 · W2 + b2  (warp per graph) ----------
__global__ void k6c_stop(const float* __restrict__ W2,
                         const float* __restrict__ b2,
                         float* __restrict__ out_stop) {
    int w = (blockIdx.x * blockDim.x + threadIdx.x) >> 5;
    int lane = threadIdx.x & 31;
    if (w >= G_N) return;
    const float4* h4 = (const float4*)(d_h1 + (size_t)w * H_N);
    const float4* w4 = (const float4*)W2;
    float s = 0.f;
    #pragma unroll
    for (int k = 0; k < 2; ++k) {
        float4 a = h4[lane + 32 * k];
        float4 b = w4[lane + 32 * k];
        s += a.x * b.x + a.y * b.y + a.z * b.z + a.w * b.w;
    }
    float tot = warp_sum(s);
    if (lane == 0) out_stop[w] = tot + b2[0];
}

// ---------------- launch -----------------------------------------------------
extern "C" void kernel_launch(void* const* d_in, const int* in_sizes, int n_in,
                              void* d_out, int out_size) {
    const float* edge_tokens     = (const float*)d_in[0];
    const float* question_tokens = (const float*)d_in[1];
    const int*   edge_batch      = (const int*)d_in[2];
    const int*   selected_mask   = (const int*)d_in[3];   // bool promoted to int32
    const float* W_edge          = (const float*)d_in[4];
    const float* W_query         = (const float*)d_in[5];
    const float* att_vec         = (const float*)d_in[6];
    const float* ln_g            = (const float*)d_in[7];
    const float* ln_b            = (const float*)d_in[8];
    const float* W1              = (const float*)d_in[9];
    const float* b1              = (const float*)d_in[10];
    const float* W2              = (const float*)d_in[11];
    const float* b2              = (const float*)d_in[12];

    float* out         = (float*)d_out;
    float* out_edge    = out;                 // [E]
    float* out_stop    = out + E_N;           // [G]
    float* out_pooled  = out + E_N + G_N;     // [G, H]

    kA_prep<<<64, 256>>>(W_edge, W_query, att_vec, edge_batch);
    k3_edges<<<K3_GRID, K3_BLOCK>>>(edge_tokens, question_tokens, edge_batch, selected_mask);
    k4_fused<<<G_N, 512>>>(selected_mask, out_edge);
    k5_pool<<<dim3(8, 8), dim3(32, 32)>>>(W_edge, out_pooled);
    k6a_ln<<<G_N, 256>>>(out_pooled, question_tokens, ln_g, ln_b);
    k6b_mlp<<<dim3(8, 8), dim3(32, 32)>>>(W1, b1);
    k6c_stop<<<(G_N * 32 + 255) / 256, 256>>>(W2, b2, out_stop);
}

// round 11
// speedup vs baseline: 1.1266x; 1.1266x over previous
#include <cuda_runtime.h>
#include <math.h>

#define E_N 500000
#define G_N 256
#define H_N 256
#define H2_N 512
#define EPS_F 1.1920929e-07f
#define LOG_EPS -15.942385f
#define SEG_CAP 2560

// ---------------- scratch (device globals; no allocation allowed) ------------
__device__ float d_v_edge[H_N];          // att_vec @ W_edge
__device__ float d_v_query[H_N];         // att_vec @ W_query
__device__ float d_q_att[G_N];           // question · v_query per graph
__device__ float d_att_raw[E_N];         // post-leaky/bonus attention logits
__device__ float d_sum_tok[G_N * H_N];   // segment sums of raw edge tokens
__device__ int   d_seg[G_N + 1];         // segment bounds (sorted edge_batch)
__device__ float d_xn[G_N * H2_N];       // LayerNorm output
__device__ float d_WeT[H_N * H_N];       // W_edge^T
__device__ float d_W1T[H2_N * H_N];      // W1^T

__device__ __forceinline__ float warp_sum(float v) {
    #pragma unroll
    for (int o = 16; o; o >>= 1) v += __shfl_xor_sync(0xffffffffu, v, o);
    return v;
}

// ---------------- kA: v-vectors + zero + transposes --------------------------
// grid 224 x 256 thr:
//   b 0-7:    v_edge cols      b 8-15:  v_query cols
//   b 16-31:  zero d_sum_tok
//   b 32-95:  W_edge^T   (64 tiles of 32x32)
//   b 96-223: W1^T       (128 tiles of 32x32)
__global__ void kA_prep(const float* __restrict__ W_edge,
                        const float* __restrict__ W_query,
                        const float* __restrict__ W1,
                        const float* __restrict__ att_vec) {
    int b = blockIdx.x;
    int tid = threadIdx.x;
    int tx = tid & 31, ty = tid >> 5;      // 32 x 8
    if (b < 16) {
        const float* W = (b < 8) ? W_edge : W_query;
        float* v       = (b < 8) ? d_v_edge : d_v_query;
        int bx = b & 7;
        __shared__ float a[H_N];
        __shared__ float part[8][32];
        a[tid] = att_vec[tid];
        __syncthreads();
        int t0 = bx * 32 + tx;
        float s = 0.f;
        #pragma unroll 8
        for (int j = ty * 32; j < ty * 32 + 32; ++j)
            s = fmaf(a[j], W[j * H_N + t0], s);
        part[ty][tx] = s;
        __syncthreads();
        if (ty == 0) {
            float r = part[0][tx] + part[1][tx] + part[2][tx] + part[3][tx]
                    + part[4][tx] + part[5][tx] + part[6][tx] + part[7][tx];
            v[t0] = r;
        }
    } else if (b < 32) {
        int idx = (b - 16) * 256 + tid;
        for (int i = idx; i < G_N * H_N; i += 16 * 256) d_sum_tok[i] = 0.0f;
    } else if (b < 96) {
        int tile = b - 32;                  // 8x8 tiles over 256x256
        int ti = tile >> 3, tj = tile & 7;
        __shared__ float t[32][33];
        #pragma unroll
        for (int r = 0; r < 4; ++r)
            t[ty * 4 + r][tx] = W_edge[(ti * 32 + ty * 4 + r) * H_N + tj * 32 + tx];
        __syncthreads();
        #pragma unroll
        for (int r = 0; r < 4; ++r)
            d_WeT[(tj * 32 + ty * 4 + r) * H_N + ti * 32 + tx] = t[tx][ty * 4 + r];
    } else {
        int tile = b - 96;                  // W1: 256x512 -> 8 row-tiles x 16 col-tiles
        int ti = tile >> 4, tj = tile & 15;
        __shared__ float t[32][33];
        #pragma unroll
        for (int r = 0; r < 4; ++r)
            t[ty * 4 + r][tx] = W1[(ti * 32 + ty * 4 + r) * H2_N + tj * 32 + tx];
        __syncthreads();
        #pragma unroll
        for (int r = 0; r < 4; ++r)
            d_W1T[(tj * 32 + ty * 4 + r) * H_N + ti * 32 + tx] = t[tx][ty * 4 + r];
    }
}

// ---------------- kB: q_att (blocks 0..31) + segment bounds (32..255) --------
__global__ void kB_qatt_seg(const float* __restrict__ q,
                            const int* __restrict__ batch) {
    int b = blockIdx.x;
    if (b < 32) {
        int w = b * 8 + (threadIdx.x >> 5);  // graph index
        int lane = threadIdx.x & 31;
        const float4* q4 = (const float4*)(q + (size_t)w * H_N);
        const float4* v4 = (const float4*)d_v_query;
        float s = 0.f;
        #pragma unroll
        for (int k = 0; k < 2; ++k) {
            float4 t = q4[lane + 32 * k];
            float4 v = v4[lane + 32 * k];
            s += t.x * v.x + t.y * v.y + t.z * v.z + t.w * v.w;
        }
        s = warp_sum(s);
        if (lane == 0) d_q_att[w] = s;
    } else {
        int idx = (b - 32) * 256 + threadIdx.x;
        int stride = (gridDim.x - 32) * 256;
        for (int e = idx; e < E_N; e += stride) {
            int bc = batch[e];
            int bp = (e == 0) ? -1 : batch[e - 1];
            for (int g = bp + 1; g <= bc; ++g) d_seg[g] = e;
            if (e == E_N - 1)
                for (int g = bc + 1; g <= G_N; ++g) d_seg[g] = E_N;
        }
    }
}

// ---------------- K3: dominant streaming pass over edge_tokens ---------------
#define K3_BLOCK 256
#define K3_GRID  592
#define K3_WARPS (K3_GRID * (K3_BLOCK / 32))

__global__ __launch_bounds__(K3_BLOCK) void k3_edges(
        const float* __restrict__ tok,
        const int* __restrict__ batch,
        const int* __restrict__ sel) {
    int warp = (blockIdx.x * blockDim.x + threadIdx.x) >> 5;
    int lane = threadIdx.x & 31;
    const int chunk = (E_N + K3_WARPS - 1) / K3_WARPS;
    int e0 = warp * chunk;
    int e1 = min(e0 + chunk, E_N);
    if (e0 >= e1) return;

    float4 v0 = ((const float4*)d_v_edge)[lane];
    float4 v1 = ((const float4*)d_v_edge)[lane + 32];

    float4 a0 = make_float4(0.f, 0.f, 0.f, 0.f);
    float4 a1 = make_float4(0.f, 0.f, 0.f, 0.f);
    float keep = 0.f;

    const float4* base = (const float4*)tok;
    float4 t0 = __ldcs(base + (size_t)e0 * 64 + lane);
    float4 t1 = __ldcs(base + (size_t)e0 * 64 + 32 + lane);
    int g  = batch[e0];
    int cg = g;

    for (int e = e0; e < e1; ++e) {
        float4 n0, n1; int ng = cg;
        if (e + 1 < e1) {
            n0 = __ldcs(base + (size_t)(e + 1) * 64 + lane);
            n1 = __ldcs(base + (size_t)(e + 1) * 64 + 32 + lane);
            ng = batch[e + 1];
        }
        if (g != cg) {  // segment boundary: flush partial sums
            float* dst = d_sum_tok + (size_t)cg * H_N;
            atomicAdd(&dst[4 * lane + 0], a0.x);
            atomicAdd(&dst[4 * lane + 1], a0.y);
            atomicAdd(&dst[4 * lane + 2], a0.z);
            atomicAdd(&dst[4 * lane + 3], a0.w);
            atomicAdd(&dst[128 + 4 * lane + 0], a1.x);
            atomicAdd(&dst[128 + 4 * lane + 1], a1.y);
            atomicAdd(&dst[128 + 4 * lane + 2], a1.z);
            atomicAdd(&dst[128 + 4 * lane + 3], a1.w);
            a0 = make_float4(0.f, 0.f, 0.f, 0.f);
            a1 = make_float4(0.f, 0.f, 0.f, 0.f);
            cg = g;
        }
        a0.x += t0.x; a0.y += t0.y; a0.z += t0.z; a0.w += t0.w;
        a1.x += t1.x; a1.y += t1.y; a1.z += t1.z; a1.w += t1.w;

        float d = t0.x * v0.x;
        d = fmaf(t0.y, v0.y, d); d = fmaf(t0.z, v0.z, d); d = fmaf(t0.w, v0.w, d);
        d = fmaf(t1.x, v1.x, d); d = fmaf(t1.y, v1.y, d);
        d = fmaf(t1.z, v1.z, d); d = fmaf(t1.w, v1.w, d);
        float tot = warp_sum(d);

        float att = tot + d_q_att[g];
        att = att > 0.f ? att : 0.2f * att;             // LeakyReLU(0.2)
        if (sel[e] == 0) att += 0.5f;                   // frontier bonus
        if (lane == (e & 31)) keep = att;

        if ((e & 31) == 31 || e == e1 - 1) {            // coalesced 128B store
            int bse = e & ~31;
            int idx = bse + lane;
            if (idx >= e0 && idx <= e)
                d_att_raw[idx] = keep;
        }

        t0 = n0; t1 = n1; g = ng;
    }
    float* dst = d_sum_tok + (size_t)cg * H_N;
    atomicAdd(&dst[4 * lane + 0], a0.x);
    atomicAdd(&dst[4 * lane + 1], a0.y);
    atomicAdd(&dst[4 * lane + 2], a0.z);
    atomicAdd(&dst[4 * lane + 3], a0.w);
    atomicAdd(&dst[128 + 4 * lane + 0], a1.x);
    atomicAdd(&dst[128 + 4 * lane + 1], a1.y);
    atomicAdd(&dst[128 + 4 * lane + 2], a1.z);
    atomicAdd(&dst[128 + 4 * lane + 3], a1.w);
}

// ---------------- K4: softmax stats + edge logits, smem-cached, 512 thr ------
__global__ __launch_bounds__(512) void k4_fused(const int* __restrict__ sel,
                                                float* __restrict__ out_edge) {
    int gi = blockIdx.x, t = threadIdx.x;
    int start = d_seg[gi], end = d_seg[gi + 1];
    int n = end - start;

    __shared__ float red[512];
    __shared__ float satt[SEG_CAP];
    __shared__ unsigned char smsk[SEG_CAP];

    if (n <= SEG_CAP) {
        #pragma unroll 4
        for (int i = t; i < n; i += 512) {
            satt[i] = d_att_raw[start + i];
            smsk[i] = (unsigned char)(sel[start + i] != 0);
        }
        __syncthreads();

        float mx = -INFINITY;
        #pragma unroll 4
        for (int i = t; i < n; i += 512) mx = fmaxf(mx, satt[i]);
        red[t] = mx; __syncthreads();
        for (int s = 256; s; s >>= 1) { if (t < s) red[t] = fmaxf(red[t], red[t + s]); __syncthreads(); }
        mx = red[0];
        __syncthreads();

        float sm = 0.f;
        #pragma unroll 4
        for (int i = t; i < n; i += 512)
            if (!smsk[i]) sm += expf(satt[i] - mx);
        red[t] = sm; __syncthreads();
        for (int s = 256; s; s >>= 1) { if (t < s) red[t] += red[t + s]; __syncthreads(); }
        float sub = mx + logf(fmaxf(red[0], EPS_F));

        #pragma unroll 4
        for (int i = t; i < n; i += 512) {
            float v = LOG_EPS;
            if (!smsk[i]) v = fmaxf(satt[i] - sub, LOG_EPS);
            out_edge[start + i] = v;
        }
    } else {
        float mx = -INFINITY;
        for (int e = start + t; e < end; e += 512) mx = fmaxf(mx, d_att_raw[e]);
        red[t] = mx; __syncthreads();
        for (int s = 256; s; s >>= 1) { if (t < s) red[t] = fmaxf(red[t], red[t + s]); __syncthreads(); }
        mx = red[0];
        __syncthreads();

        float sm = 0.f;
        for (int e = start + t; e < end; e += 512)
            if (sel[e] == 0) sm += expf(d_att_raw[e] - mx);
        red[t] = sm; __syncthreads();
        for (int s = 256; s; s >>= 1) { if (t < s) red[t] += red[t + s]; __syncthreads(); }
        float sub = mx + logf(fmaxf(red[0], EPS_F));

        for (int e = start + t; e < end; e += 512) {
            float v = LOG_EPS;
            if (sel[e] == 0) v = fmaxf(d_att_raw[e] - sub, LOG_EPS);
            out_edge[e] = v;
        }
    }
}

// ---------------- K5': pool row-GEMM (WeT, coalesced) + LayerNorm ------------
// grid 128 x 512 thr; 2 graphs per block (half = tid>>8, j = tid&255)
__global__ __launch_bounds__(512) void k5_pool_ln(
        const float* __restrict__ q,
        const float* __restrict__ ln_g,
        const float* __restrict__ ln_b,
        float* __restrict__ out_pool) {
    int tid = threadIdx.x;
    int half = tid >> 8, j = tid & 255;
    int g = 2 * blockIdx.x + half;

    __shared__ float s[2][H_N];
    __shared__ float rs[512], rss[512];

    s[half][j] = d_sum_tok[(size_t)g * H_N + j];
    __syncthreads();

    const float* sh = s[half];
    float acc0 = 0.f, acc1 = 0.f, acc2 = 0.f, acc3 = 0.f;
    #pragma unroll 8
    for (int k = 0; k < H_N; k += 4) {
        acc0 = fmaf(sh[k + 0], d_WeT[(k + 0) * H_N + j], acc0);
        acc1 = fmaf(sh[k + 1], d_WeT[(k + 1) * H_N + j], acc1);
        acc2 = fmaf(sh[k + 2], d_WeT[(k + 2) * H_N + j], acc2);
        acc3 = fmaf(sh[k + 3], d_WeT[(k + 3) * H_N + j], acc3);
    }
    float invden = 1.0f / (float)max(d_seg[g + 1] - d_seg[g], 1);
    float pooled = (acc0 + acc1 + acc2 + acc3) * invden;
    out_pool[(size_t)g * H_N + j] = pooled;

    float x1 = q[(size_t)g * H_N + j];
    rs[tid]  = pooled + x1;
    rss[tid] = pooled * pooled + x1 * x1;
    __syncthreads();
    for (int st = 128; st; st >>= 1) {
        if (j < st) {
            rs[half * 256 + j]  += rs[half * 256 + j + st];
            rss[half * 256 + j] += rss[half * 256 + j + st];
        }
        __syncthreads();
    }
    float mu  = rs[half * 256] * (1.0f / 512.0f);
    float var = rss[half * 256] * (1.0f / 512.0f) - mu * mu;
    float inv = rsqrtf(var + 1e-5f);
    d_xn[(size_t)g * H2_N + j]       = (pooled - mu) * inv * ln_g[j]       + ln_b[j];
    d_xn[(size_t)g * H2_N + 256 + j] = (x1 - mu)     * inv * ln_g[256 + j] + ln_b[256 + j];
}

// ---------------- K6': MLP row-GEMM (W1T) + GELU + stop dot ------------------
// grid 128 x 512 thr; 2 graphs per block
__global__ __launch_bounds__(512) void k6_mlp_stop(
        const float* __restrict__ b1,
        const float* __restrict__ W2,
        const float* __restrict__ b2,
        float* __restrict__ out_stop) {
    int tid = threadIdx.x;
    int half = tid >> 8, j = tid & 255;
    int g = 2 * blockIdx.x + half;

    __shared__ float xn[2][H2_N];
    __shared__ float red[512];

    #pragma unroll
    for (int i = tid; i < 2 * H2_N; i += 512)
        xn[i >> 9][i & 511] = d_xn[(size_t)(2 * blockIdx.x) * H2_N + i];
    __syncthreads();

    const float* xh = xn[half];
    float acc0 = 0.f, acc1 = 0.f, acc2 = 0.f, acc3 = 0.f;
    #pragma unroll 8
    for (int k = 0; k < H2_N; k += 4) {
        acc0 = fmaf(xh[k + 0], d_W1T[(k + 0) * H_N + j], acc0);
        acc1 = fmaf(xh[k + 1], d_W1T[(k + 1) * H_N + j], acc1);
        acc2 = fmaf(xh[k + 2], d_W1T[(k + 2) * H_N + j], acc2);
        acc3 = fmaf(xh[k + 3], d_W1T[(k + 3) * H_N + j], acc3);
    }
    float x = acc0 + acc1 + acc2 + acc3 + b1[j];
    float h = 0.5f * x * (1.0f + erff(x * 0.70710678118654752f)); // exact GELU

    red[tid] = h * W2[j];
    __syncthreads();
    for (int st = 128; st; st >>= 1) {
        if (j < st) red[half * 256 + j] += red[half * 256 + j + st];
        __syncthreads();
    }
    if (j == 0) out_stop[g] = red[half * 256] + b2[0];
}

// ---------------- launch -----------------------------------------------------
extern "C" void kernel_launch(void* const* d_in, const int* in_sizes, int n_in,
                              void* d_out, int out_size) {
    const float* edge_tokens     = (const float*)d_in[0];
    const float* question_tokens = (const float*)d_in[1];
    const int*   edge_batch      = (const int*)d_in[2];
    const int*   selected_mask   = (const int*)d_in[3];   // bool promoted to int32
    const float* W_edge          = (const float*)d_in[4];
    const float* W_query         = (const float*)d_in[5];
    const float* att_vec         = (const float*)d_in[6];
    const float* ln_g            = (const float*)d_in[7];
    const float* ln_b            = (const float*)d_in[8];
    const float* W1              = (const float*)d_in[9];
    const float* b1              = (const float*)d_in[10];
    const float* W2              = (const float*)d_in[11];
    const float* b2              = (const float*)d_in[12];

    float* out         = (float*)d_out;
    float* out_edge    = out;                 // [E]
    float* out_stop    = out + E_N;           // [G]
    float* out_pooled  = out + E_N + G_N;     // [G, H]

    kA_prep<<<224, 256>>>(W_edge, W_query, W1, att_vec);
    kB_qatt_seg<<<256, 256>>>(question_tokens, edge_batch);
    k3_edges<<<K3_GRID, K3_BLOCK>>>(edge_tokens, edge_batch, selected_mask);
    k4_fused<<<G_N, 512>>>(selected_mask, out_edge);
    k5_pool_ln<<<G_N / 2, 512>>>(question_tokens, ln_g, ln_b, out_pooled);
    k6_mlp_stop<<<G_N / 2, 512>>>(b1, W2, b2, out_stop);
}

// round 12
// speedup vs baseline: 1.1639x; 1.0330x over previous
#include <cuda_runtime.h>
#include <math.h>

#define E_N 500000
#define G_N 256
#define H_N 256
#define H2_N 512
#define EPS_F 1.1920929e-07f
#define LOG_EPS -15.942385f
#define SEG_CAP 2560

// ---------------- scratch (device globals; no allocation allowed) ------------
__device__ float d_v_edge[H_N];          // att_vec @ W_edge
__device__ float d_v_query[H_N];         // att_vec @ W_query
__device__ float d_q_att[G_N];           // question · v_query per graph
__device__ float d_att_raw[E_N];         // post-leaky/bonus attention logits
__device__ float d_sum_tok[G_N * H_N];   // segment sums of raw edge tokens
__device__ int   d_seg[G_N + 1];         // segment bounds (sorted edge_batch)
__device__ float d_xn[G_N * H2_N];       // LayerNorm output
__device__ float d_WeT[H_N * H_N];       // W_edge^T
__device__ float d_W1T[H2_N * H_N];      // W1^T

__device__ __forceinline__ float warp_sum(float v) {
    #pragma unroll
    for (int o = 16; o; o >>= 1) v += __shfl_xor_sync(0xffffffffu, v, o);
    return v;
}
__device__ __forceinline__ float warp_max(float v) {
    #pragma unroll
    for (int o = 16; o; o >>= 1) v = fmaxf(v, __shfl_xor_sync(0xffffffffu, v, o));
    return v;
}

// ---------------- kA: v-vectors + zero + transposes --------------------------
// grid 224 x 256 thr:
//   b 0-7: v_edge   b 8-15: v_query   b 16-31: zero sum_tok
//   b 32-95: W_edge^T    b 96-223: W1^T
__global__ void kA_prep(const float* __restrict__ W_edge,
                        const float* __restrict__ W_query,
                        const float* __restrict__ W1,
                        const float* __restrict__ att_vec) {
    int b = blockIdx.x;
    int tid = threadIdx.x;
    int tx = tid & 31, ty = tid >> 5;      // 32 x 8
    if (b < 16) {
        const float* W = (b < 8) ? W_edge : W_query;
        float* v       = (b < 8) ? d_v_edge : d_v_query;
        int bx = b & 7;
        __shared__ float a[H_N];
        __shared__ float part[8][32];
        a[tid] = att_vec[tid];
        __syncthreads();
        int t0 = bx * 32 + tx;
        float s = 0.f;
        #pragma unroll 8
        for (int j = ty * 32; j < ty * 32 + 32; ++j)
            s = fmaf(a[j], W[j * H_N + t0], s);
        part[ty][tx] = s;
        __syncthreads();
        if (ty == 0) {
            float r = part[0][tx] + part[1][tx] + part[2][tx] + part[3][tx]
                    + part[4][tx] + part[5][tx] + part[6][tx] + part[7][tx];
            v[t0] = r;
        }
    } else if (b < 32) {
        int idx = (b - 16) * 256 + tid;
        for (int i = idx; i < G_N * H_N; i += 16 * 256) d_sum_tok[i] = 0.0f;
    } else if (b < 96) {
        int tile = b - 32;                  // 8x8 tiles over 256x256
        int ti = tile >> 3, tj = tile & 7;
        __shared__ float t[32][33];
        #pragma unroll
        for (int r = 0; r < 4; ++r)
            t[ty * 4 + r][tx] = W_edge[(ti * 32 + ty * 4 + r) * H_N + tj * 32 + tx];
        __syncthreads();
        #pragma unroll
        for (int r = 0; r < 4; ++r)
            d_WeT[(tj * 32 + ty * 4 + r) * H_N + ti * 32 + tx] = t[tx][ty * 4 + r];
    } else {
        int tile = b - 96;                  // W1: 256x512 -> 8 x 16 tiles
        int ti = tile >> 4, tj = tile & 15;
        __shared__ float t[32][33];
        #pragma unroll
        for (int r = 0; r < 4; ++r)
            t[ty * 4 + r][tx] = W1[(ti * 32 + ty * 4 + r) * H2_N + tj * 32 + tx];
        __syncthreads();
        #pragma unroll
        for (int r = 0; r < 4; ++r)
            d_W1T[(tj * 32 + ty * 4 + r) * H_N + ti * 32 + tx] = t[tx][ty * 4 + r];
    }
}

// ---------------- kB: q_att (blocks 0..31) + segment bounds (32..255) --------
__global__ void kB_qatt_seg(const float* __restrict__ q,
                            const int* __restrict__ batch) {
    int b = blockIdx.x;
    if (b < 32) {
        int w = b * 8 + (threadIdx.x >> 5);  // graph index
        int lane = threadIdx.x & 31;
        const float4* q4 = (const float4*)(q + (size_t)w * H_N);
        const float4* v4 = (const float4*)d_v_query;
        float s = 0.f;
        #pragma unroll
        for (int k = 0; k < 2; ++k) {
            float4 t = q4[lane + 32 * k];
            float4 v = v4[lane + 32 * k];
            s += t.x * v.x + t.y * v.y + t.z * v.z + t.w * v.w;
        }
        s = warp_sum(s);
        if (lane == 0) d_q_att[w] = s;
    } else {
        int idx = (b - 32) * 256 + threadIdx.x;
        int stride = (gridDim.x - 32) * 256;
        for (int e = idx; e < E_N; e += stride) {
            int bc = batch[e];
            int bp = (e == 0) ? -1 : batch[e - 1];
            for (int g = bp + 1; g <= bc; ++g) d_seg[g] = e;
            if (e == E_N - 1)
                for (int g = bc + 1; g <= G_N; ++g) d_seg[g] = E_N;
        }
    }
}

// ---------------- K3: dominant streaming pass, depth-2 prefetch --------------
#define K3_BLOCK 256
#define K3_GRID  592
#define K3_WARPS (K3_GRID * (K3_BLOCK / 32))

__global__ __launch_bounds__(K3_BLOCK) void k3_edges(
        const float* __restrict__ tok,
        const int* __restrict__ batch,
        const int* __restrict__ sel) {
    int warp = (blockIdx.x * blockDim.x + threadIdx.x) >> 5;
    int lane = threadIdx.x & 31;
    const int chunk = (E_N + K3_WARPS - 1) / K3_WARPS;
    int e0 = warp * chunk;
    int e1 = min(e0 + chunk, E_N);
    if (e0 >= e1) return;

    float4 v0 = ((const float4*)d_v_edge)[lane];
    float4 v1 = ((const float4*)d_v_edge)[lane + 32];

    float4 a0 = make_float4(0.f, 0.f, 0.f, 0.f);
    float4 a1 = make_float4(0.f, 0.f, 0.f, 0.f);
    float keep = 0.f;

    const float4* base = (const float4*)tok;
    // pipeline regs: t = edge e, u = edge e+1
    float4 t0 = __ldcs(base + (size_t)e0 * 64 + lane);
    float4 t1 = __ldcs(base + (size_t)e0 * 64 + 32 + lane);
    int gt = batch[e0];
    float4 u0 = t0, u1 = t1;
    int gu = gt;
    if (e0 + 1 < e1) {
        u0 = __ldcs(base + (size_t)(e0 + 1) * 64 + lane);
        u1 = __ldcs(base + (size_t)(e0 + 1) * 64 + 32 + lane);
        gu = batch[e0 + 1];
    }
    int cg = gt;

    for (int e = e0; e < e1; ++e) {
        // prefetch edge e+2
        float4 p0 = u0, p1 = u1; int gp = gu;
        if (e + 2 < e1) {
            p0 = __ldcs(base + (size_t)(e + 2) * 64 + lane);
            p1 = __ldcs(base + (size_t)(e + 2) * 64 + 32 + lane);
            gp = batch[e + 2];
        }
        if (gt != cg) {  // segment boundary: flush partial sums
            float* dst = d_sum_tok + (size_t)cg * H_N;
            atomicAdd(&dst[4 * lane + 0], a0.x);
            atomicAdd(&dst[4 * lane + 1], a0.y);
            atomicAdd(&dst[4 * lane + 2], a0.z);
            atomicAdd(&dst[4 * lane + 3], a0.w);
            atomicAdd(&dst[128 + 4 * lane + 0], a1.x);
            atomicAdd(&dst[128 + 4 * lane + 1], a1.y);
            atomicAdd(&dst[128 + 4 * lane + 2], a1.z);
            atomicAdd(&dst[128 + 4 * lane + 3], a1.w);
            a0 = make_float4(0.f, 0.f, 0.f, 0.f);
            a1 = make_float4(0.f, 0.f, 0.f, 0.f);
            cg = gt;
        }
        a0.x += t0.x; a0.y += t0.y; a0.z += t0.z; a0.w += t0.w;
        a1.x += t1.x; a1.y += t1.y; a1.z += t1.z; a1.w += t1.w;

        float d = t0.x * v0.x;
        d = fmaf(t0.y, v0.y, d); d = fmaf(t0.z, v0.z, d); d = fmaf(t0.w, v0.w, d);
        d = fmaf(t1.x, v1.x, d); d = fmaf(t1.y, v1.y, d);
        d = fmaf(t1.z, v1.z, d); d = fmaf(t1.w, v1.w, d);
        float tot = warp_sum(d);

        float att = tot + d_q_att[gt];
        att = att > 0.f ? att : 0.2f * att;             // LeakyReLU(0.2)
        if (sel[e] == 0) att += 0.5f;                   // frontier bonus
        if (lane == (e & 31)) keep = att;

        if ((e & 31) == 31 || e == e1 - 1) {            // coalesced 128B store
            int bse = e & ~31;
            int idx = bse + lane;
            if (idx >= e0 && idx <= e)
                d_att_raw[idx] = keep;
        }

        t0 = u0; t1 = u1; gt = gu;
        u0 = p0; u1 = p1; gu = gp;
    }
    float* dst = d_sum_tok + (size_t)cg * H_N;
    atomicAdd(&dst[4 * lane + 0], a0.x);
    atomicAdd(&dst[4 * lane + 1], a0.y);
    atomicAdd(&dst[4 * lane + 2], a0.z);
    atomicAdd(&dst[4 * lane + 3], a0.w);
    atomicAdd(&dst[128 + 4 * lane + 0], a1.x);
    atomicAdd(&dst[128 + 4 * lane + 1], a1.y);
    atomicAdd(&dst[128 + 4 * lane + 2], a1.z);
    atomicAdd(&dst[128 + 4 * lane + 3], a1.w);
}

// ---------------- K45: fused k4 (softmax+logits) & k5 (pool GEMM + LN) -------
// grid 384 x 512 thr: blocks 0-255 -> k4 role (graph=blockIdx); 256-383 -> k5.
__global__ __launch_bounds__(512) void k45_fused(
        const int* __restrict__ sel,
        const float* __restrict__ q,
        const float* __restrict__ ln_g,
        const float* __restrict__ ln_b,
        float* __restrict__ out_edge,
        float* __restrict__ out_pool) {
    int tid = threadIdx.x;
    int lane = tid & 31, wid = tid >> 5;   // 16 warps

    if (blockIdx.x < 256) {
        // ================= k4 role: segment softmax + logits =================
        int gi = blockIdx.x;
        int start = d_seg[gi], end = d_seg[gi + 1];
        int n = end - start;

        __shared__ float wred[16];
        __shared__ float bcast;
        __shared__ float satt[SEG_CAP];
        __shared__ unsigned char smsk[SEG_CAP];

        if (n <= SEG_CAP) {
            #pragma unroll 4
            for (int i = tid; i < n; i += 512) {
                satt[i] = d_att_raw[start + i];
                smsk[i] = (unsigned char)(sel[start + i] != 0);
            }
            __syncthreads();

            // max reduction: warp shuffle + 16-wide cross-warp
            float mx = -INFINITY;
            #pragma unroll 4
            for (int i = tid; i < n; i += 512) mx = fmaxf(mx, satt[i]);
            mx = warp_max(mx);
            if (lane == 0) wred[wid] = mx;
            __syncthreads();
            if (wid == 0) {
                float v = (lane < 16) ? wred[lane] : -INFINITY;
                v = warp_max(v);
                if (lane == 0) bcast = v;
            }
            __syncthreads();
            mx = bcast;

            float sm = 0.f;
            #pragma unroll 4
            for (int i = tid; i < n; i += 512)
                if (!smsk[i]) sm += expf(satt[i] - mx);
            sm = warp_sum(sm);
            if (lane == 0) wred[wid] = sm;
            __syncthreads();
            if (wid == 0) {
                float v = (lane < 16) ? wred[lane] : 0.f;
                v = warp_sum(v);
                if (lane == 0) bcast = mx + logf(fmaxf(v, EPS_F));
            }
            __syncthreads();
            float sub = bcast;

            #pragma unroll 4
            for (int i = tid; i < n; i += 512) {
                float v = LOG_EPS;
                if (!smsk[i]) v = fmaxf(satt[i] - sub, LOG_EPS);
                out_edge[start + i] = v;
            }
        } else {
            // fallback: global passes
            float mx = -INFINITY;
            for (int e = start + tid; e < end; e += 512) mx = fmaxf(mx, d_att_raw[e]);
            mx = warp_max(mx);
            if (lane == 0) wred[wid] = mx;
            __syncthreads();
            if (wid == 0) {
                float v = (lane < 16) ? wred[lane] : -INFINITY;
                v = warp_max(v);
                if (lane == 0) bcast = v;
            }
            __syncthreads();
            mx = bcast;

            float sm = 0.f;
            for (int e = start + tid; e < end; e += 512)
                if (sel[e] == 0) sm += expf(d_att_raw[e] - mx);
            sm = warp_sum(sm);
            if (lane == 0) wred[wid] = sm;
            __syncthreads();
            if (wid == 0) {
                float v = (lane < 16) ? wred[lane] : 0.f;
                v = warp_sum(v);
                if (lane == 0) bcast = mx + logf(fmaxf(v, EPS_F));
            }
            __syncthreads();
            float sub = bcast;

            for (int e = start + tid; e < end; e += 512) {
                float v = LOG_EPS;
                if (sel[e] == 0) v = fmaxf(d_att_raw[e] - sub, LOG_EPS);
                out_edge[e] = v;
            }
        }
    } else {
        // ================= k5 role: pool row-GEMM + LayerNorm ================
        int blk = blockIdx.x - 256;            // 0..127
        int half = tid >> 8, j = tid & 255;
        int g = 2 * blk + half;

        __shared__ float s[2][H_N];
        __shared__ float rs[512], rss[512];

        s[half][j] = d_sum_tok[(size_t)g * H_N + j];
        __syncthreads();

        const float* sh = s[half];
        float acc0 = 0.f, acc1 = 0.f, acc2 = 0.f, acc3 = 0.f;
        #pragma unroll 8
        for (int k = 0; k < H_N; k += 4) {
            acc0 = fmaf(sh[k + 0], d_WeT[(k + 0) * H_N + j], acc0);
            acc1 = fmaf(sh[k + 1], d_WeT[(k + 1) * H_N + j], acc1);
            acc2 = fmaf(sh[k + 2], d_WeT[(k + 2) * H_N + j], acc2);
            acc3 = fmaf(sh[k + 3], d_WeT[(k + 3) * H_N + j], acc3);
        }
        float invden = 1.0f / (float)max(d_seg[g + 1] - d_seg[g], 1);
        float pooled = (acc0 + acc1 + acc2 + acc3) * invden;
        out_pool[(size_t)g * H_N + j] = pooled;

        float x1 = q[(size_t)g * H_N + j];
        rs[tid]  = pooled + x1;
        rss[tid] = pooled * pooled + x1 * x1;
        __syncthreads();
        for (int st = 128; st; st >>= 1) {
            if (j < st) {
                rs[half * 256 + j]  += rs[half * 256 + j + st];
                rss[half * 256 + j] += rss[half * 256 + j + st];
            }
            __syncthreads();
        }
        float mu  = rs[half * 256] * (1.0f / 512.0f);
        float var = rss[half * 256] * (1.0f / 512.0f) - mu * mu;
        float inv = rsqrtf(var + 1e-5f);
        d_xn[(size_t)g * H2_N + j]       = (pooled - mu) * inv * ln_g[j]       + ln_b[j];
        d_xn[(size_t)g * H2_N + 256 + j] = (x1 - mu)     * inv * ln_g[256 + j] + ln_b[256 + j];
    }
}

// ---------------- K6': MLP row-GEMM (W1T) + GELU + stop dot ------------------
// grid 128 x 512 thr; 2 graphs per block
__global__ __launch_bounds__(512) void k6_mlp_stop(
        const float* __restrict__ b1,
        const float* __restrict__ W2,
        const float* __restrict__ b2,
        float* __restrict__ out_stop) {
    int tid = threadIdx.x;
    int half = tid >> 8, j = tid & 255;
    int g = 2 * blockIdx.x + half;

    __shared__ float xn[2][H2_N];
    __shared__ float red[512];

    #pragma unroll
    for (int i = tid; i < 2 * H2_N; i += 512)
        xn[i >> 9][i & 511] = d_xn[(size_t)(2 * blockIdx.x) * H2_N + i];
    __syncthreads();

    const float* xh = xn[half];
    float acc0 = 0.f, acc1 = 0.f, acc2 = 0.f, acc3 = 0.f;
    #pragma unroll 8
    for (int k = 0; k < H2_N; k += 4) {
        acc0 = fmaf(xh[k + 0], d_W1T[(k + 0) * H_N + j], acc0);
        acc1 = fmaf(xh[k + 1], d_W1T[(k + 1) * H_N + j], acc1);
        acc2 = fmaf(xh[k + 2], d_W1T[(k + 2) * H_N + j], acc2);
        acc3 = fmaf(xh[k + 3], d_W1T[(k + 3) * H_N + j], acc3);
    }
    float x = acc0 + acc1 + acc2 + acc3 + b1[j];
    float h = 0.5f * x * (1.0f + erff(x * 0.70710678118654752f)); // exact GELU

    red[tid] = h * W2[j];
    __syncthreads();
    for (int st = 128; st; st >>= 1) {
        if (j < st) red[half * 256 + j] += red[half * 256 + j + st];
        __syncthreads();
    }
    if (j == 0) out_stop[g] = red[half * 256] + b2[0];
}

// ---------------- launch -----------------------------------------------------
extern "C" void kernel_launch(void* const* d_in, const int* in_sizes, int n_in,
                              void* d_out, int out_size) {
    const float* edge_tokens     = (const float*)d_in[0];
    const float* question_tokens = (const float*)d_in[1];
    const int*   edge_batch      = (const int*)d_in[2];
    const int*   selected_mask   = (const int*)d_in[3];   // bool promoted to int32
    const float* W_edge          = (const float*)d_in[4];
    const float* W_query         = (const float*)d_in[5];
    const float* att_vec         = (const float*)d_in[6];
    const float* ln_g            = (const float*)d_in[7];
    const float* ln_b            = (const float*)d_in[8];
    const float* W1              = (const float*)d_in[9];
    const float* b1              = (const float*)d_in[10];
    const float* W2              = (const float*)d_in[11];
    const float* b2              = (const float*)d_in[12];

    float* out         = (float*)d_out;
    float* out_edge    = out;                 // [E]
    float* out_stop    = out + E_N;           // [G]
    float* out_pooled  = out + E_N + G_N;     // [G, H]

    kA_prep<<<224, 256>>>(W_edge, W_query, W1, att_vec);
    kB_qatt_seg<<<256, 256>>>(question_tokens, edge_batch);
    k3_edges<<<K3_GRID, K3_BLOCK>>>(edge_tokens, edge_batch, selected_mask);
    k45_fused<<<384, 512>>>(selected_mask, question_tokens, ln_g, ln_b,
                            out_edge, out_pooled);
    k6_mlp_stop<<<G_N / 2, 512>>>(b1, W2, b2, out_stop);
}